// round 1
// baseline (speedup 1.0000x reference)
#include <cuda_runtime.h>

#define BATCH 128
#define DG 512
#define DH 1024
#define LAM 0.95f
#define ETA 0.5f
#define LN_EPS 1e-5f

// Scratch state (allocation-free): base pre-activation, current h, matvec result y.
__device__ float g_base[BATCH * DH];
__device__ float g_h[BATCH * DH];
__device__ float g_y[BATCH * DH];

// ---------------------------------------------------------------------------
// Kernel 1: base[b][n] = sum_k h_prev[b][k]*W_h[n][k] + sum_k z[b][k]*W_g[n][k] + b_h[n]
// Tiled 32x32x32 GEMM over concatenated K = 1024 (W_h) + 512 (W_g).
// grid = (4 batch tiles, 32 col tiles), 256 threads, 2x2 outputs per thread.
// ---------------------------------------------------------------------------
__global__ void base_gemm_kernel(const float* __restrict__ Hp,
                                 const float* __restrict__ Z,
                                 const float* __restrict__ Wh,
                                 const float* __restrict__ Wg,
                                 const float* __restrict__ bh)
{
    __shared__ float Hs[32][33];
    __shared__ float Ws[32][33];

    const int tid = threadIdx.x;
    const int tx = tid & 15;
    const int ty = tid >> 4;
    const int bm0 = blockIdx.x * 32;   // batch tile
    const int n0  = blockIdx.y * 32;   // output-col tile

    float acc00 = 0.f, acc01 = 0.f, acc10 = 0.f, acc11 = 0.f;

    for (int k0 = 0; k0 < DH + DG; k0 += 32) {
        const float* src;
        const float* wsrc;
        int K, kk0;
        if (k0 < DH) { src = Hp; wsrc = Wh; K = DH; kk0 = k0; }
        else         { src = Z;  wsrc = Wg; K = DG; kk0 = k0 - DH; }

        #pragma unroll
        for (int l = 0; l < 4; l++) {
            int idx = tid + l * 256;
            int r = idx >> 5, c = idx & 31;
            Hs[r][c] = src[(bm0 + r) * K + kk0 + c];
            Ws[r][c] = wsrc[(n0 + r) * K + kk0 + c];
        }
        __syncthreads();

        #pragma unroll
        for (int kk = 0; kk < 32; kk++) {
            float h0 = Hs[ty * 2][kk];
            float h1 = Hs[ty * 2 + 1][kk];
            float w0 = Ws[tx * 2][kk];
            float w1 = Ws[tx * 2 + 1][kk];
            acc00 += h0 * w0; acc01 += h0 * w1;
            acc10 += h1 * w0; acc11 += h1 * w1;
        }
        __syncthreads();
    }

    const int r0 = bm0 + ty * 2;
    const int c0 = n0 + tx * 2;
    const float bias0 = bh[c0];
    const float bias1 = bh[c0 + 1];
    g_base[r0 * DH + c0]           = acc00 + bias0;
    g_base[r0 * DH + c0 + 1]       = acc01 + bias1;
    g_base[(r0 + 1) * DH + c0]     = acc10 + bias0;
    g_base[(r0 + 1) * DH + c0 + 1] = acc11 + bias1;
}

// ---------------------------------------------------------------------------
// Kernel 2: h = relu(LN(base [+ y])) per batch. grid=128, block=256 (float4 each).
// ---------------------------------------------------------------------------
__global__ void ln_relu_kernel(const float* __restrict__ gamma,
                               const float* __restrict__ beta,
                               int has_y)
{
    const int b = blockIdx.x;
    const int t = threadIdx.x;

    float4 x = reinterpret_cast<const float4*>(g_base + b * DH)[t];
    if (has_y) {
        float4 y = reinterpret_cast<const float4*>(g_y + b * DH)[t];
        x.x += y.x; x.y += y.y; x.z += y.z; x.w += y.w;
    }

    float s  = x.x + x.y + x.z + x.w;
    float ss = x.x * x.x + x.y * x.y + x.z * x.z + x.w * x.w;

    #pragma unroll
    for (int o = 16; o > 0; o >>= 1) {
        s  += __shfl_xor_sync(0xffffffffu, s,  o);
        ss += __shfl_xor_sync(0xffffffffu, ss, o);
    }

    __shared__ float sm_s[8], sm_ss[8];
    const int w = t >> 5, lane = t & 31;
    if (lane == 0) { sm_s[w] = s; sm_ss[w] = ss; }
    __syncthreads();
    if (w == 0) {
        float a  = (lane < 8) ? sm_s[lane]  : 0.f;
        float bq = (lane < 8) ? sm_ss[lane] : 0.f;
        #pragma unroll
        for (int o = 4; o > 0; o >>= 1) {
            a  += __shfl_xor_sync(0xffffffffu, a,  o);
            bq += __shfl_xor_sync(0xffffffffu, bq, o);
        }
        if (lane == 0) { sm_s[0] = a; sm_ss[0] = bq; }
    }
    __syncthreads();

    const float mu   = sm_s[0] * (1.0f / DH);
    const float var  = sm_ss[0] * (1.0f / DH) - mu * mu;
    const float rstd = rsqrtf(var + LN_EPS);

    float4 g  = reinterpret_cast<const float4*>(gamma)[t];
    float4 be = reinterpret_cast<const float4*>(beta)[t];
    float4 h;
    h.x = fmaxf(0.f, (x.x - mu) * rstd * g.x + be.x);
    h.y = fmaxf(0.f, (x.y - mu) * rstd * g.y + be.y);
    h.z = fmaxf(0.f, (x.z - mu) * rstd * g.z + be.z);
    h.w = fmaxf(0.f, (x.w - mu) * rstd * g.w + be.w);
    reinterpret_cast<float4*>(g_h + b * DH)[t] = h;
}

// ---------------------------------------------------------------------------
// Kernel 3: y[b] = A[b] @ h[b]. grid = (16 row-chunks, 128 batches), 256 thr.
// Warp-per-row, float4 streaming loads, 4 accumulators for MLP.
// ---------------------------------------------------------------------------
__global__ void matvec_kernel(const float* __restrict__ A)
{
    const int b = blockIdx.y;
    const int chunk = blockIdx.x;
    const int t = threadIdx.x;

    __shared__ float4 hs4[256];
    hs4[t] = reinterpret_cast<const float4*>(g_h + b * DH)[t];
    __syncthreads();

    const int w = t >> 5, lane = t & 31;
    const float4* __restrict__ Ab =
        reinterpret_cast<const float4*>(A + (size_t)b * DH * DH);

    #pragma unroll
    for (int r8 = 0; r8 < 8; r8++) {
        const int row = chunk * 64 + w * 8 + r8;
        const float4* __restrict__ Ar = Ab + row * 256;

        float a0 = 0.f, a1 = 0.f, a2 = 0.f, a3 = 0.f;
        #pragma unroll
        for (int it = 0; it < 8; it += 4) {
            float4 v0 = Ar[lane + (it + 0) * 32];
            float4 v1 = Ar[lane + (it + 1) * 32];
            float4 v2 = Ar[lane + (it + 2) * 32];
            float4 v3 = Ar[lane + (it + 3) * 32];
            float4 h0 = hs4[lane + (it + 0) * 32];
            float4 h1 = hs4[lane + (it + 1) * 32];
            float4 h2 = hs4[lane + (it + 2) * 32];
            float4 h3 = hs4[lane + (it + 3) * 32];
            a0 += v0.x * h0.x + v0.y * h0.y + v0.z * h0.z + v0.w * h0.w;
            a1 += v1.x * h1.x + v1.y * h1.y + v1.z * h1.z + v1.w * h1.w;
            a2 += v2.x * h2.x + v2.y * h2.y + v2.z * h2.z + v2.w * h2.w;
            a3 += v3.x * h3.x + v3.y * h3.y + v3.z * h3.z + v3.w * h3.w;
        }
        float acc = (a0 + a1) + (a2 + a3);
        #pragma unroll
        for (int o = 16; o > 0; o >>= 1)
            acc += __shfl_xor_sync(0xffffffffu, acc, o);
        if (lane == 0) g_y[b * DH + row] = acc;
    }
}

// ---------------------------------------------------------------------------
// Kernel 4: A_k = LAM*A + ETA*h hᵀ streamed to output; also emits h_t.
// grid = (64 row-chunks of 16, 128 batches), 256 thr, float4 in/out.
// ---------------------------------------------------------------------------
__global__ void update_kernel(const float* __restrict__ A,
                              float* __restrict__ outH,
                              float* __restrict__ outA)
{
    const int b = blockIdx.y;
    const int chunk = blockIdx.x;
    const int t = threadIdx.x;

    __shared__ float4 hs4[256];
    hs4[t] = reinterpret_cast<const float4*>(g_h + b * DH)[t];
    __syncthreads();
    const float* hsf = reinterpret_cast<const float*>(hs4);

    if (chunk == 0)
        reinterpret_cast<float4*>(outH + b * DH)[t] = hs4[t];

    const float4* __restrict__ Ab =
        reinterpret_cast<const float4*>(A + (size_t)b * DH * DH);
    float4* __restrict__ Ob =
        reinterpret_cast<float4*>(outA + (size_t)b * DH * DH);

    const float4 hv = hs4[t];  // h[b][4t..4t+3] — the column chunk this thread owns

    #pragma unroll
    for (int r = 0; r < 16; r++) {
        const int row = chunk * 16 + r;
        const float hi = hsf[row] * ETA;
        float4 a = Ab[row * 256 + t];
        float4 o;
        o.x = LAM * a.x + hi * hv.x;
        o.y = LAM * a.y + hi * hv.y;
        o.z = LAM * a.z + hi * hv.z;
        o.w = LAM * a.w + hi * hv.w;
        Ob[row * 256 + t] = o;
    }
}

// ---------------------------------------------------------------------------
extern "C" void kernel_launch(void* const* d_in, const int* in_sizes, int n_in,
                              void* d_out, int out_size)
{
    const float* z      = (const float*)d_in[0];
    const float* h_prev = (const float*)d_in[1];
    const float* A_prev = (const float*)d_in[2];
    const float* W_h    = (const float*)d_in[3];
    const float* W_g    = (const float*)d_in[4];
    const float* b_h    = (const float*)d_in[5];
    const float* gamma  = (const float*)d_in[6];
    const float* beta   = (const float*)d_in[7];

    float* outH = (float*)d_out;                 // h_t: 128*1024
    float* outA = (float*)d_out + BATCH * DH;    // A_k: 128*1024*1024

    base_gemm_kernel<<<dim3(BATCH / 32, DH / 32), 256>>>(h_prev, z, W_h, W_g, b_h);
    ln_relu_kernel<<<BATCH, 256>>>(gamma, beta, /*has_y=*/0);

    for (int s = 0; s < 3; s++) {
        matvec_kernel<<<dim3(16, BATCH), 256>>>(A_prev);
        ln_relu_kernel<<<BATCH, 256>>>(gamma, beta, /*has_y=*/1);
    }

    update_kernel<<<dim3(64, BATCH), 256>>>(A_prev, outH, outA);
}